// round 2
// baseline (speedup 1.0000x reference)
#include <cuda_runtime.h>
#include <cuda_bf16.h>
#include <cstdint>

// ContrastiveLoss: B=4096 rows, F=256 features, output = scalar fp32 loss.
//
// loss = -mean(pos_sim)/T + [ (1/T)*sum_offdiag(s) - (2B-1)*sum_i LSE_i ] / (4B^2)
// with s = C C^T (C = normalized [n1;n2], 8192x256), LSE_i = log(sum_{j!=i} exp(s_ij/T)).
// T = 0.1. No max-subtraction needed: |s/T| <= ~10.5, exp fits fp32 comfortably.

#define BROWS 4096
#define FDIM  256
#define TBROWS 8192            // 2B
#define BM 64
#define BN 64
#define SSTRB 528              // smem row stride in BYTES (264 bf16): conflict-free for ldmatrix
#define SPLIT 2                // column halves per row-tile (deterministic rowE without atomics)
#define NJT (TBROWS / BN / SPLIT) // 64 col tiles per block

// ---------------- scratch (no allocations allowed) ----------------
__device__ __align__(16) __nv_bfloat16 g_Cb[TBROWS * FDIM];   // 4 MB normalized bf16
__device__ float g_rowE[SPLIT][TBROWS];                        // partial exp-sums per row
__device__ float g_sPart[256];                                 // per-block sum of off-diag s
__device__ float g_posPart[512];                               // per-block sum of pos_sim

// ---------------- kernel 1: normalize + pos similarity ----------------
__device__ __forceinline__ uint2 pack4_bf16(float4 v, float s) {
    __nv_bfloat162 lo = __float22bfloat162_rn(make_float2(v.x * s, v.y * s));
    __nv_bfloat162 hi = __float22bfloat162_rn(make_float2(v.z * s, v.w * s));
    uint2 r;
    r.x = *reinterpret_cast<uint32_t*>(&lo);
    r.y = *reinterpret_cast<uint32_t*>(&hi);
    return r;
}

__global__ void __launch_bounds__(256) normalize_kernel(
    const float* __restrict__ x1, const float* __restrict__ x2)
{
    int warp = threadIdx.x >> 5;
    int lane = threadIdx.x & 31;
    int r = blockIdx.x * 8 + warp;             // row in [0, 4096)

    const float4* a4 = reinterpret_cast<const float4*>(x1 + (size_t)r * FDIM);
    const float4* b4 = reinterpret_cast<const float4*>(x2 + (size_t)r * FDIM);
    float4 a0 = a4[lane], a1 = a4[lane + 32];
    float4 b0 = b4[lane], b1 = b4[lane + 32];

    float ss1 = a0.x*a0.x + a0.y*a0.y + a0.z*a0.z + a0.w*a0.w
              + a1.x*a1.x + a1.y*a1.y + a1.z*a1.z + a1.w*a1.w;
    float ss2 = b0.x*b0.x + b0.y*b0.y + b0.z*b0.z + b0.w*b0.w
              + b1.x*b1.x + b1.y*b1.y + b1.z*b1.z + b1.w*b1.w;
    float dt  = a0.x*b0.x + a0.y*b0.y + a0.z*b0.z + a0.w*b0.w
              + a1.x*b1.x + a1.y*b1.y + a1.z*b1.z + a1.w*b1.w;

    #pragma unroll
    for (int o = 16; o > 0; o >>= 1) {
        ss1 += __shfl_xor_sync(0xffffffffu, ss1, o);
        ss2 += __shfl_xor_sync(0xffffffffu, ss2, o);
        dt  += __shfl_xor_sync(0xffffffffu, dt,  o);
    }

    float inv1 = 1.0f / fmaxf(sqrtf(ss1), 1e-7f);
    float inv2 = 1.0f / fmaxf(sqrtf(ss2), 1e-7f);

    uint2* o1 = reinterpret_cast<uint2*>(g_Cb + (size_t)r * FDIM);
    uint2* o2 = reinterpret_cast<uint2*>(g_Cb + (size_t)(r + BROWS) * FDIM);
    o1[lane]      = pack4_bf16(a0, inv1);
    o1[lane + 32] = pack4_bf16(a1, inv1);
    o2[lane]      = pack4_bf16(b0, inv2);
    o2[lane + 32] = pack4_bf16(b1, inv2);

    // pos similarity partial (deterministic: per-block fixed-order sum)
    __shared__ float ps[8];
    if (lane == 0) ps[warp] = dt * inv1 * inv2;
    __syncthreads();
    if (threadIdx.x == 0) {
        float s = 0.0f;
        #pragma unroll
        for (int i = 0; i < 8; i++) s += ps[i];
        g_posPart[blockIdx.x] = s;
    }
}

// ---------------- kernel 2: fused GEMM + exp-sum epilogue ----------------
#define LDM4(R, ADDR) \
    asm volatile("ldmatrix.sync.aligned.m8n8.x4.shared.b16 {%0,%1,%2,%3}, [%4];" \
        : "=r"((R)[0]), "=r"((R)[1]), "=r"((R)[2]), "=r"((R)[3]) : "r"(ADDR))

#define MMA16816(ACC, RA, B0, B1) \
    asm volatile("mma.sync.aligned.m16n8k16.row.col.f32.bf16.bf16.f32 " \
        "{%0,%1,%2,%3},{%4,%5,%6,%7},{%8,%9},{%0,%1,%2,%3};" \
        : "+f"((ACC)[0]), "+f"((ACC)[1]), "+f"((ACC)[2]), "+f"((ACC)[3]) \
        : "r"((RA)[0]), "r"((RA)[1]), "r"((RA)[2]), "r"((RA)[3]), "r"(B0), "r"(B1))

extern __shared__ char smem_raw[];

__device__ __forceinline__ void load_tile(char* dst, int r0, int tid) {
    const uint4* G = reinterpret_cast<const uint4*>(g_Cb);
    #pragma unroll
    for (int i = 0; i < 8; i++) {
        int idx = tid + i * 256;
        int row = idx >> 5;
        int c   = idx & 31;                     // 16B chunk within the 512B row
        *reinterpret_cast<uint4*>(dst + row * SSTRB + c * 16) =
            G[(size_t)(r0 + row) * 32 + c];
    }
}

__global__ void __launch_bounds__(256, 2) sim_kernel() {
    const int tid     = threadIdx.x;
    const int rowTile = blockIdx.x >> 1;       // 0..127
    const int half    = blockIdx.x & 1;        // column half
    const int warp    = tid >> 5;
    const int lane    = tid & 31;
    const int wm      = warp >> 2;             // 0..1  (M)
    const int wn      = warp & 3;              // 0..3  (N)
    const int grp     = lane >> 2;             // 0..7
    const int qid     = lane & 3;              // 0..3

    char* As = smem_raw;
    char* Bs = smem_raw + BM * SSTRB;

    load_tile(As, rowTile * BM, tid);

    const uint32_t sA = (uint32_t)__cvta_generic_to_shared(As);
    const uint32_t sB = (uint32_t)__cvta_generic_to_shared(Bs);
    const uint32_t aBase0 = sA + (uint32_t)(wm * 32 + (lane & 15)) * SSTRB + (lane >> 4) * 16;
    const uint32_t aBase1 = aBase0 + 16u * SSTRB;
    const uint32_t bBase  = sB + (uint32_t)(wn * 16 + (lane & 15)) * SSTRB + (lane >> 4) * 16;

    float rsum[4] = {0.f, 0.f, 0.f, 0.f};      // running exp-sums, rows: f*16 + h*8 + grp
    float ssum = 0.f;                           // running sum of off-diag s

    for (int jt = 0; jt < NJT; jt++) {
        const int jtg = half * NJT + jt;        // global col tile
        __syncthreads();                        // prior ldmatrix reads of Bs done
        load_tile(Bs, jtg * BN, tid);
        __syncthreads();

        float acc[2][2][4];
        #pragma unroll
        for (int f = 0; f < 2; f++)
            #pragma unroll
            for (int nf = 0; nf < 2; nf++)
                #pragma unroll
                for (int k = 0; k < 4; k++) acc[f][nf][k] = 0.f;

        #pragma unroll
        for (int kk = 0; kk < 16; kk++) {
            uint32_t ra0[4], ra1[4], rb[4];
            LDM4(ra0, aBase0 + kk * 32);
            LDM4(ra1, aBase1 + kk * 32);
            LDM4(rb,  bBase  + kk * 32);
            MMA16816(acc[0][0], ra0, rb[0], rb[2]);
            MMA16816(acc[0][1], ra0, rb[1], rb[3]);
            MMA16816(acc[1][0], ra1, rb[0], rb[2]);
            MMA16816(acc[1][1], ra1, rb[1], rb[3]);
        }

        // epilogue: logits = 10*s; accumulate exp + s, skipping the diagonal
        const bool dg = (jtg == rowTile);       // only this tile can contain diag
        #pragma unroll
        for (int f = 0; f < 2; f++) {
            #pragma unroll
            for (int nf = 0; nf < 2; nf++) {
                const float* a = acc[f][nf];
                int m0 = wm * 32 + f * 16 + grp;           // local row (upper)
                int n0 = wn * 16 + nf * 8 + 2 * qid;       // local col
                if (!dg || (m0 != n0))          { ssum += a[0]; rsum[f*2+0] += __expf(a[0] * 10.0f); }
                if (!dg || (m0 != n0 + 1))      { ssum += a[1]; rsum[f*2+0] += __expf(a[1] * 10.0f); }
                if (!dg || (m0 + 8 != n0))      { ssum += a[2]; rsum[f*2+1] += __expf(a[2] * 10.0f); }
                if (!dg || (m0 + 8 != n0 + 1))  { ssum += a[3]; rsum[f*2+1] += __expf(a[3] * 10.0f); }
            }
        }
    }

    // ---- reduce rsum across the 4 lanes sharing a row (qid dimension) ----
    #pragma unroll
    for (int i = 0; i < 4; i++) {
        rsum[i] += __shfl_xor_sync(0xffffffffu, rsum[i], 1);
        rsum[i] += __shfl_xor_sync(0xffffffffu, rsum[i], 2);
    }
    #pragma unroll
    for (int o = 16; o > 0; o >>= 1) ssum += __shfl_xor_sync(0xffffffffu, ssum, o);

    __syncthreads();                            // smem tiles no longer needed: reuse
    float* rb_buf = reinterpret_cast<float*>(smem_raw);   // [64][4]
    float* ws_buf = rb_buf + 256;                          // [8]
    if ((lane & 3) == 0) {
        #pragma unroll
        for (int f = 0; f < 2; f++)
            #pragma unroll
            for (int h = 0; h < 2; h++)
                rb_buf[(wm * 32 + f * 16 + h * 8 + grp) * 4 + wn] = rsum[f * 2 + h];
    }
    if (lane == 0) ws_buf[warp] = ssum;
    __syncthreads();

    if (tid < 64) {
        float e = rb_buf[tid*4] + rb_buf[tid*4+1] + rb_buf[tid*4+2] + rb_buf[tid*4+3];
        g_rowE[half][rowTile * BM + tid] = e;
    }
    if (tid == 0) {
        float s = 0.f;
        #pragma unroll
        for (int i = 0; i < 8; i++) s += ws_buf[i];
        g_sPart[blockIdx.x] = s;
    }
}

// ---------------- kernel 3: finalize ----------------
__global__ void __launch_bounds__(256) finalize_kernel(float* __restrict__ out) {
    const int tid = threadIdx.x;
    __shared__ float buf[8];

    float lsum = 0.f;
    for (int i = tid; i < TBROWS; i += 256)
        lsum += logf(g_rowE[0][i] + g_rowE[1][i]);
    float ssum = g_sPart[tid];                  // exactly 256 entries
    float psum = g_posPart[tid] + g_posPart[tid + 256];

    // deterministic block reduce (shuffle + fixed-order warp-partial sum)
    float vals[3] = {lsum, ssum, psum};
    float tot[3];
    #pragma unroll
    for (int v = 0; v < 3; v++) {
        float x = vals[v];
        #pragma unroll
        for (int o = 16; o > 0; o >>= 1) x += __shfl_xor_sync(0xffffffffu, x, o);
        if ((tid & 31) == 0) buf[tid >> 5] = x;
        __syncthreads();
        float r = 0.f;
        if (tid == 0) {
            #pragma unroll
            for (int i = 0; i < 8; i++) r += buf[i];
        }
        __syncthreads();
        tot[v] = r;
    }

    if (tid == 0) {
        double logSum = tot[0];
        double sSum   = tot[1];
        double posSum = tot[2];
        double negMean = (10.0 * sSum - (double)(TBROWS - 1) * logSum)
                       / (4.0 * (double)BROWS * (double)BROWS);
        double loss = -(posSum / (double)BROWS) * 10.0 + negMean;
        out[0] = (float)loss;
    }
}

// ---------------- launch ----------------
extern "C" void kernel_launch(void* const* d_in, const int* in_sizes, int n_in,
                              void* d_out, int out_size) {
    const float* x1 = (const float*)d_in[0];
    const float* x2 = (const float*)d_in[1];
    float* out = (float*)d_out;

    normalize_kernel<<<512, 256>>>(x1, x2);

    const int smemBytes = 2 * BM * SSTRB;       // 67584 B — needs opt-in
    cudaFuncSetAttribute(sim_kernel, cudaFuncAttributeMaxDynamicSharedMemorySize, smemBytes);
    sim_kernel<<<256, 256, smemBytes>>>();

    finalize_kernel<<<1, 256>>>(out);
}

// round 4
// speedup vs baseline: 1.1987x; 1.1987x over previous
#include <cuda_runtime.h>
#include <cuda_bf16.h>
#include <cstdint>

// ContrastiveLoss B=4096, F=256.
// loss = -mean(pos)/T + [10*sum_offdiag(s) - (2B-1)*sum_i LSE_i]/(4B^2),
// s = C C^T, C = row-normalized [n1;n2] (8192x256, bf16). |10*s| <= ~10.5 so plain exp-sum is safe.
// sim kernel: mma.sync m16n8k16 bf16, 128x128 block tile, K=256 resident,
// cp.async double-buffered column tiles (prefetch depth 2), fused exp epilogue.

#define BROWS  4096
#define FDIM   256
#define TBROWS 8192
#define TM     128                     // block tile M = N
#define NTILES 64                      // 8192/128
#define SPLIT  2
#define NJT    (NTILES / SPLIT)        // 32 col tiles per block
#define GROWB  512                     // gmem row bytes (256 bf16)
#define SSTR   528                     // smem row stride bytes (+1 16B phase/row: conflict-free ldmatrix)
#define TILE_SM (TM * SSTR)            // 67584
#define TILE_GM (TM * GROWB)           // 65536

// ---------------- scratch ----------------
__device__ __align__(16) __nv_bfloat16 g_Cb[TBROWS * FDIM];   // 4 MB normalized bf16, row-major
__device__ float g_rowE[SPLIT][TBROWS];
__device__ float g_sPart[NTILES * SPLIT];   // 128
__device__ float g_posPart[512];

// ================= kernel 1: normalize + pos sim (unchanged from passing R2) =================
__device__ __forceinline__ uint2 pack4_bf16(float4 v, float s) {
    __nv_bfloat162 lo = __float22bfloat162_rn(make_float2(v.x * s, v.y * s));
    __nv_bfloat162 hi = __float22bfloat162_rn(make_float2(v.z * s, v.w * s));
    uint2 r;
    r.x = *reinterpret_cast<uint32_t*>(&lo);
    r.y = *reinterpret_cast<uint32_t*>(&hi);
    return r;
}

__global__ void __launch_bounds__(256) normalize_kernel(
    const float* __restrict__ x1, const float* __restrict__ x2)
{
    int warp = threadIdx.x >> 5, lane = threadIdx.x & 31;
    int r = blockIdx.x * 8 + warp;
    const float4* a4 = reinterpret_cast<const float4*>(x1 + (size_t)r * FDIM);
    const float4* b4 = reinterpret_cast<const float4*>(x2 + (size_t)r * FDIM);
    float4 a0 = a4[lane], a1 = a4[lane + 32];
    float4 b0 = b4[lane], b1 = b4[lane + 32];

    float ss1 = a0.x*a0.x+a0.y*a0.y+a0.z*a0.z+a0.w*a0.w + a1.x*a1.x+a1.y*a1.y+a1.z*a1.z+a1.w*a1.w;
    float ss2 = b0.x*b0.x+b0.y*b0.y+b0.z*b0.z+b0.w*b0.w + b1.x*b1.x+b1.y*b1.y+b1.z*b1.z+b1.w*b1.w;
    float dt  = a0.x*b0.x+a0.y*b0.y+a0.z*b0.z+a0.w*b0.w + a1.x*b1.x+a1.y*b1.y+a1.z*b1.z+a1.w*b1.w;
    #pragma unroll
    for (int o = 16; o > 0; o >>= 1) {
        ss1 += __shfl_xor_sync(~0u, ss1, o);
        ss2 += __shfl_xor_sync(~0u, ss2, o);
        dt  += __shfl_xor_sync(~0u, dt,  o);
    }
    float inv1 = 1.0f / fmaxf(sqrtf(ss1), 1e-7f);
    float inv2 = 1.0f / fmaxf(sqrtf(ss2), 1e-7f);

    uint2* o1 = reinterpret_cast<uint2*>(g_Cb + (size_t)r * FDIM);
    uint2* o2 = reinterpret_cast<uint2*>(g_Cb + (size_t)(r + BROWS) * FDIM);
    o1[lane]      = pack4_bf16(a0, inv1);
    o1[lane + 32] = pack4_bf16(a1, inv1);
    o2[lane]      = pack4_bf16(b0, inv2);
    o2[lane + 32] = pack4_bf16(b1, inv2);

    __shared__ float ps[8];
    if (lane == 0) ps[warp] = dt * inv1 * inv2;
    __syncthreads();
    if (threadIdx.x == 0) {
        float s = 0.f;
        #pragma unroll
        for (int i = 0; i < 8; i++) s += ps[i];
        g_posPart[blockIdx.x] = s;
    }
}

// ================= helpers =================
__device__ __forceinline__ uint32_t smem_u32(const void* p) {
    uint32_t a;
    asm("{ .reg .u64 t; cvta.to.shared.u64 t, %1; cvt.u32.u64 %0, t; }" : "=r"(a) : "l"(p));
    return a;
}
#define CP16(dst, src) \
    asm volatile("cp.async.cg.shared.global [%0], [%1], 16;" :: "r"(dst), "l"(src) : "memory")
#define CP_COMMIT() asm volatile("cp.async.commit_group;" ::: "memory")
#define CP_WAIT1()  asm volatile("cp.async.wait_group 1;" ::: "memory")

#define LDM4(R, ADDR) \
    asm volatile("ldmatrix.sync.aligned.m8n8.x4.shared.b16 {%0,%1,%2,%3}, [%4];" \
        : "=r"((R)[0]), "=r"((R)[1]), "=r"((R)[2]), "=r"((R)[3]) : "r"(ADDR))

#define MMA16816(ACC, RA, B0, B1) \
    asm volatile("mma.sync.aligned.m16n8k16.row.col.f32.bf16.bf16.f32 " \
        "{%0,%1,%2,%3},{%4,%5,%6,%7},{%8,%9},{%0,%1,%2,%3};" \
        : "+f"((ACC)[0]), "+f"((ACC)[1]), "+f"((ACC)[2]), "+f"((ACC)[3]) \
        : "r"((RA)[0]), "r"((RA)[1]), "r"((RA)[2]), "r"((RA)[3]), "r"(B0), "r"(B1))

// copy one 128-row tile: gmem row-major 512B/row -> smem stride 528B
__device__ __forceinline__ void cp_tile(uint32_t dstBase, const char* src, int tid) {
    #pragma unroll
    for (int i = 0; i < 16; i++) {
        int idx = tid + i * 256;
        int row = idx >> 5, c = idx & 31;
        CP16(dstBase + row * SSTR + c * 16, src + row * GROWB + c * 16);
    }
}

// SMEM: A tile, then two B stages
#define SM_A  0
#define SM_B0 TILE_SM
#define SM_B1 (2 * TILE_SM)
#define SM_TOTAL (3 * TILE_SM)   // 202752

// ================= kernel 2: pipelined GEMM + exp epilogue =================
__global__ void __launch_bounds__(256, 1) sim_kernel() {
    extern __shared__ char smem[];
    const uint32_t sb = smem_u32(smem);
    const int tid = threadIdx.x, warp = tid >> 5, lane = tid & 31;
    const int wm = warp >> 2, wn = warp & 3;       // 2 x 4 warp grid, warp tile 64x32
    const int grp = lane >> 2, qid = lane & 3;
    const int rt = blockIdx.x >> 1, half = blockIdx.x & 1;

    const char* gC = reinterpret_cast<const char*>(g_Cb);
    const char* Asrc = gC + (size_t)rt * TILE_GM;

    cp_tile(sb + SM_A,  Asrc, tid);
    cp_tile(sb + SM_B0, gC + (size_t)(half * NJT + 0) * TILE_GM, tid);
    CP_COMMIT();                                   // group: A + t0
    cp_tile(sb + SM_B1, gC + (size_t)(half * NJT + 1) * TILE_GM, tid);
    CP_COMMIT();                                   // group: t1

    // lane-fixed ldmatrix offsets (16 rows x 16B halves)
    const uint32_t lrow = lane & 15, lhi = (lane >> 4) * 16;
    uint32_t aOff[4], bOff[2];
    #pragma unroll
    for (int mf = 0; mf < 4; mf++) aOff[mf] = sb + SM_A + (wm * 64 + mf * 16 + lrow) * SSTR + lhi;
    #pragma unroll
    for (int h = 0; h < 2; h++)    bOff[h] = (wn * 32 + h * 16 + lrow) * SSTR + lhi;

    float rsum[8];
    #pragma unroll
    for (int i = 0; i < 8; i++) rsum[i] = 0.f;
    float ssum = 0.f;

    for (int jt = 0; jt < NJT; jt++) {
        CP_WAIT1();
        __syncthreads();                            // tile jt resident in buf[jt&1]
        const uint32_t bB = sb + ((jt & 1) ? SM_B1 : SM_B0);

        float acc[4][4][4];
        #pragma unroll
        for (int mf = 0; mf < 4; mf++)
            #pragma unroll
            for (int nf = 0; nf < 4; nf++)
                #pragma unroll
                for (int k = 0; k < 4; k++) acc[mf][nf][k] = 0.f;

        #pragma unroll
        for (int kk = 0; kk < 16; kk++) {
            uint32_t ra[4][4], rb[2][4];
            #pragma unroll
            for (int mf = 0; mf < 4; mf++) LDM4(ra[mf], aOff[mf] + kk * 32);
            #pragma unroll
            for (int h = 0; h < 2; h++)    LDM4(rb[h], bB + bOff[h] + kk * 32);
            #pragma unroll
            for (int mf = 0; mf < 4; mf++) {
                #pragma unroll
                for (int h = 0; h < 2; h++) {
                    MMA16816(acc[mf][2*h+0], ra[mf], rb[h][0], rb[h][2]);
                    MMA16816(acc[mf][2*h+1], ra[mf], rb[h][1], rb[h][3]);
                }
            }
        }
        __syncthreads();                            // everyone done reading buf[jt&1]
        if (jt + 2 < NJT) {                         // prefetch t_{jt+2} into the buffer just freed
            cp_tile(bB, gC + (size_t)(half * NJT + jt + 2) * TILE_GM, tid);
            CP_COMMIT();
        }

        // epilogue (register-only; overlaps in-flight cp.async)
        const bool dg = (half * NJT + jt) == rt;
        #pragma unroll
        for (int mf = 0; mf < 4; mf++) {
            #pragma unroll
            for (int nf = 0; nf < 4; nf++) {
                #pragma unroll
                for (int k = 0; k < 4; k++) {
                    float x = acc[mf][nf][k];
                    if (!dg || (wm*64 + mf*16 + grp + (k >> 1)*8) != (wn*32 + nf*8 + 2*qid + (k & 1))) {
                        ssum += x;
                        rsum[mf*2 + (k >> 1)] += exp2f(x * 14.426950408889634f); // exp(10x)
                    }
                }
            }
        }
    }

    // ---- reduce row exp-sums: over qid lanes, then over wn warps via smem ----
    #pragma unroll
    for (int i = 0; i < 8; i++) {
        rsum[i] += __shfl_xor_sync(~0u, rsum[i], 1);
        rsum[i] += __shfl_xor_sync(~0u, rsum[i], 2);
    }
    #pragma unroll
    for (int o = 16; o > 0; o >>= 1) ssum += __shfl_xor_sync(~0u, ssum, o);

    __syncthreads();                                // smem tiles dead; reuse A region
    float* re = reinterpret_cast<float*>(smem);     // [128][4]
    float* ws = re + 512;                           // [8]
    if (qid == 0) {
        #pragma unroll
        for (int mf = 0; mf < 4; mf++)
            #pragma unroll
            for (int h = 0; h < 2; h++)
                re[(wm*64 + mf*16 + h*8 + grp) * 4 + wn] = rsum[mf*2 + h];
    }
    if (lane == 0) ws[warp] = ssum;
    __syncthreads();

    if (tid < TM)
        g_rowE[half][rt * TM + tid] = re[tid*4] + re[tid*4+1] + re[tid*4+2] + re[tid*4+3];
    if (tid == 0) {
        float s = 0.f;
        #pragma unroll
        for (int i = 0; i < 8; i++) s += ws[i];
        g_sPart[blockIdx.x] = s;
    }
}

// ================= kernel 3: finalize =================
__global__ void __launch_bounds__(256) finalize_kernel(float* __restrict__ out) {
    const int tid = threadIdx.x;
    __shared__ float buf[8];
    float lsum = 0.f;
    for (int i = tid; i < TBROWS; i += 256)
        lsum += logf(g_rowE[0][i] + g_rowE[1][i]);
    float ssum = (tid < NTILES * SPLIT) ? g_sPart[tid] : 0.f;
    float psum = g_posPart[tid] + g_posPart[tid + 256];

    float vals[3] = {lsum, ssum, psum};
    float tot[3];
    #pragma unroll
    for (int v = 0; v < 3; v++) {
        float x = vals[v];
        #pragma unroll
        for (int o = 16; o > 0; o >>= 1) x += __shfl_xor_sync(~0u, x, o);
        if ((tid & 31) == 0) buf[tid >> 5] = x;
        __syncthreads();
        float r = 0.f;
        if (tid == 0) {
            #pragma unroll
            for (int i = 0; i < 8; i++) r += buf[i];
        }
        __syncthreads();
        tot[v] = r;
    }
    if (tid == 0) {
        double logSum = tot[0], sSum = tot[1], posSum = tot[2];
        double negMean = (10.0 * sSum - (double)(TBROWS - 1) * logSum)
                       / (4.0 * (double)BROWS * (double)BROWS);
        out[0] = (float)(-(posSum / (double)BROWS) * 10.0 + negMean);
    }
}

// ================= launch =================
extern "C" void kernel_launch(void* const* d_in, const int* in_sizes, int n_in,
                              void* d_out, int out_size) {
    const float* x1 = (const float*)d_in[0];
    const float* x2 = (const float*)d_in[1];
    float* out = (float*)d_out;

    normalize_kernel<<<512, 256>>>(x1, x2);
    cudaFuncSetAttribute(sim_kernel, cudaFuncAttributeMaxDynamicSharedMemorySize, SM_TOTAL);
    sim_kernel<<<NTILES * SPLIT, 256, SM_TOTAL>>>();
    finalize_kernel<<<1, 256>>>(out);
}

// round 5
// speedup vs baseline: 2.1779x; 1.8169x over previous
#include <cuda_runtime.h>
#include <cuda_bf16.h>
#include <cstdint>

// ContrastiveLoss B=4096, F=256.
// loss = -mean(pos)/T + [10*sum_offdiag(s) - (2B-1)*sum_i LSE_i]/(4B^2),
// s = C C^T (symmetric!), C = row-normalized [n1;n2] (8192x256 bf16).
// R5: only upper-triangle 128x128 tiles (2080 of 4096). Off-diag tile exp feeds
// rowE[row] AND rowE[col] (symmetry), ssum gets 2x. mma.sync bf16 + cp.async pipeline.

#define BROWS  4096
#define FDIM   256
#define TBROWS 8192
#define TM     128
#define NTILES 64                      // 8192/128
#define NPAIRS 2080                    // 64*65/2
#define GRID_S 148
#define GROWB  512                     // gmem row bytes
#define SSTR   528                     // smem row stride (conflict-free ldmatrix)
#define TILE_SM (TM * SSTR)            // 67584
#define TILE_GM (TM * GROWB)           // 65536

// ---------------- scratch ----------------
__device__ __align__(16) __nv_bfloat16 g_Cb[TBROWS * FDIM];
__device__ float g_rowE[TBROWS];           // atomically accumulated exp row-sums
__device__ float g_sPart[256];             // per-block sum of off-diag s (x2 counted)
__device__ float g_posPart[512];

// ================= kernel 1: normalize + pos sim + zero rowE =================
__device__ __forceinline__ uint2 pack4_bf16(float4 v, float s) {
    __nv_bfloat162 lo = __float22bfloat162_rn(make_float2(v.x * s, v.y * s));
    __nv_bfloat162 hi = __float22bfloat162_rn(make_float2(v.z * s, v.w * s));
    uint2 r;
    r.x = *reinterpret_cast<uint32_t*>(&lo);
    r.y = *reinterpret_cast<uint32_t*>(&hi);
    return r;
}

__global__ void __launch_bounds__(256) normalize_kernel(
    const float* __restrict__ x1, const float* __restrict__ x2)
{
    int gid = blockIdx.x * 256 + threadIdx.x;
    if (gid < TBROWS) g_rowE[gid] = 0.f;      // fresh accumulators every launch/replay

    int warp = threadIdx.x >> 5, lane = threadIdx.x & 31;
    int r = blockIdx.x * 8 + warp;
    const float4* a4 = reinterpret_cast<const float4*>(x1 + (size_t)r * FDIM);
    const float4* b4 = reinterpret_cast<const float4*>(x2 + (size_t)r * FDIM);
    float4 a0 = a4[lane], a1 = a4[lane + 32];
    float4 b0 = b4[lane], b1 = b4[lane + 32];

    float ss1 = a0.x*a0.x+a0.y*a0.y+a0.z*a0.z+a0.w*a0.w + a1.x*a1.x+a1.y*a1.y+a1.z*a1.z+a1.w*a1.w;
    float ss2 = b0.x*b0.x+b0.y*b0.y+b0.z*b0.z+b0.w*b0.w + b1.x*b1.x+b1.y*b1.y+b1.z*b1.z+b1.w*b1.w;
    float dt  = a0.x*b0.x+a0.y*b0.y+a0.z*b0.z+a0.w*b0.w + a1.x*b1.x+a1.y*b1.y+a1.z*b1.z+a1.w*b1.w;
    #pragma unroll
    for (int o = 16; o > 0; o >>= 1) {
        ss1 += __shfl_xor_sync(~0u, ss1, o);
        ss2 += __shfl_xor_sync(~0u, ss2, o);
        dt  += __shfl_xor_sync(~0u, dt,  o);
    }
    float inv1 = 1.0f / fmaxf(sqrtf(ss1), 1e-7f);
    float inv2 = 1.0f / fmaxf(sqrtf(ss2), 1e-7f);

    uint2* o1 = reinterpret_cast<uint2*>(g_Cb + (size_t)r * FDIM);
    uint2* o2 = reinterpret_cast<uint2*>(g_Cb + (size_t)(r + BROWS) * FDIM);
    o1[lane]      = pack4_bf16(a0, inv1);
    o1[lane + 32] = pack4_bf16(a1, inv1);
    o2[lane]      = pack4_bf16(b0, inv2);
    o2[lane + 32] = pack4_bf16(b1, inv2);

    __shared__ float ps[8];
    if (lane == 0) ps[warp] = dt * inv1 * inv2;
    __syncthreads();
    if (threadIdx.x == 0) {
        float s = 0.f;
        #pragma unroll
        for (int i = 0; i < 8; i++) s += ps[i];
        g_posPart[blockIdx.x] = s;
    }
}

// ================= helpers =================
__device__ __forceinline__ uint32_t smem_u32(const void* p) {
    uint32_t a;
    asm("{ .reg .u64 t; cvta.to.shared.u64 t, %1; cvt.u32.u64 %0, t; }" : "=r"(a) : "l"(p));
    return a;
}
#define CP16(dst, src) \
    asm volatile("cp.async.cg.shared.global [%0], [%1], 16;" :: "r"(dst), "l"(src) : "memory")
#define CP_COMMIT() asm volatile("cp.async.commit_group;" ::: "memory")
#define CP_WAIT0()  asm volatile("cp.async.wait_group 0;" ::: "memory")
#define CP_WAIT1()  asm volatile("cp.async.wait_group 1;" ::: "memory")

#define LDM4(R, ADDR) \
    asm volatile("ldmatrix.sync.aligned.m8n8.x4.shared.b16 {%0,%1,%2,%3}, [%4];" \
        : "=r"((R)[0]), "=r"((R)[1]), "=r"((R)[2]), "=r"((R)[3]) : "r"(ADDR))

#define MMA16816(ACC, RA, B0, B1) \
    asm volatile("mma.sync.aligned.m16n8k16.row.col.f32.bf16.bf16.f32 " \
        "{%0,%1,%2,%3},{%4,%5,%6,%7},{%8,%9},{%0,%1,%2,%3};" \
        : "+f"((ACC)[0]), "+f"((ACC)[1]), "+f"((ACC)[2]), "+f"((ACC)[3]) \
        : "r"((RA)[0]), "r"((RA)[1]), "r"((RA)[2]), "r"((RA)[3]), "r"(B0), "r"(B1))

__device__ __forceinline__ void cp_tile(uint32_t dstBase, const char* src, int tid) {
    #pragma unroll
    for (int i = 0; i < 16; i++) {
        int idx = tid + i * 256;
        int row = idx >> 5, c = idx & 31;
        CP16(dstBase + row * SSTR + c * 16, src + row * GROWB + c * 16);
    }
}

__device__ __forceinline__ void stepPair(int& it, int& jt) {
    if (++jt == NTILES) { ++it; jt = it; }
}

#define SM_A  0
#define SM_B0 TILE_SM
#define SM_B1 (2 * TILE_SM)
#define SM_TOTAL (3 * TILE_SM)   // 202752

// ================= kernel 2: triangle GEMM + symmetric exp epilogue =================
__global__ void __launch_bounds__(256, 1) sim_kernel() {
    extern __shared__ char smem[];
    const uint32_t sb = smem_u32(smem);
    const int tid = threadIdx.x, warp = tid >> 5, lane = tid & 31;
    const int wm = warp >> 2, wn = warp & 3;
    const int grp = lane >> 2, qid = lane & 3;
    const int b = blockIdx.x;

    // contiguous chunk of the row-major triangle pair list
    const int cnt = 14 + (b < 8);
    const int p0  = b * 14 + (b < 8 ? b : 8);
    int itC = 0, cum = 0;
    while (cum + (NTILES - itC) <= p0) { cum += NTILES - itC; ++itC; }
    int jtC = itC + (p0 - cum);
    int itN = itC, jtN = jtC;  stepPair(itN, jtN);
    int itN2 = itN, jtN2 = jtN; stepPair(itN2, jtN2);

    const char* gC = reinterpret_cast<const char*>(g_Cb);

    cp_tile(sb + SM_A,  gC + (size_t)itC * TILE_GM, tid);
    cp_tile(sb + SM_B0, gC + (size_t)jtC * TILE_GM, tid);
    CP_COMMIT();                                    // g0: A0 + B0
    cp_tile(sb + SM_B1, gC + (size_t)jtN * TILE_GM, tid);
    CP_COMMIT();                                    // g1: B1

    const uint32_t lrow = lane & 15, lhi = (lane >> 4) * 16;
    uint32_t aOff[4], bOff[2];
    #pragma unroll
    for (int mf = 0; mf < 4; mf++) aOff[mf] = sb + SM_A + (wm * 64 + mf * 16 + lrow) * SSTR + lhi;
    #pragma unroll
    for (int h = 0; h < 2; h++)    bOff[h] = (wn * 32 + h * 16 + lrow) * SSTR + lhi;

    float ssum = 0.f;
    bool aFresh = false;

    for (int t = 0; t < cnt; t++) {
        if (aFresh) CP_WAIT0(); else CP_WAIT1();
        __syncthreads();
        const uint32_t bB = sb + ((t & 1) ? SM_B1 : SM_B0);

        float acc[4][4][4];
        #pragma unroll
        for (int mf = 0; mf < 4; mf++)
            #pragma unroll
            for (int nf = 0; nf < 4; nf++)
                #pragma unroll
                for (int k = 0; k < 4; k++) acc[mf][nf][k] = 0.f;

        #pragma unroll
        for (int kk = 0; kk < 16; kk++) {
            uint32_t ra[4][4], rb[2][4];
            #pragma unroll
            for (int mf = 0; mf < 4; mf++) LDM4(ra[mf], aOff[mf] + kk * 32);
            #pragma unroll
            for (int h = 0; h < 2; h++)    LDM4(rb[h], bB + bOff[h] + kk * 32);
            #pragma unroll
            for (int mf = 0; mf < 4; mf++) {
                #pragma unroll
                for (int h = 0; h < 2; h++) {
                    MMA16816(acc[mf][2*h+0], ra[mf], rb[h][0], rb[h][2]);
                    MMA16816(acc[mf][2*h+1], ra[mf], rb[h][1], rb[h][3]);
                }
            }
        }
        __syncthreads();                             // done reading A and B[t&1]

        // prefetch group for tile t+2 (B) and t+1 (A, if row tile changes)
        bool nextAFresh = false;
        if (t + 2 < cnt) cp_tile(bB, gC + (size_t)jtN2 * TILE_GM, tid);
        if (t + 1 < cnt && itN != itC) {
            cp_tile(sb + SM_A, gC + (size_t)itN * TILE_GM, tid);
            nextAFresh = true;
        }
        CP_COMMIT();

        // ---- epilogue: exp + symmetric accumulation ----
        const bool dg = (itC == jtC);
        float rs[8], cs[8];
        #pragma unroll
        for (int i = 0; i < 8; i++) { rs[i] = 0.f; cs[i] = 0.f; }

        #pragma unroll
        for (int mf = 0; mf < 4; mf++) {
            #pragma unroll
            for (int nf = 0; nf < 4; nf++) {
                #pragma unroll
                for (int k = 0; k < 4; k++) {
                    float x = acc[mf][nf][k];
                    int rl = wm*64 + mf*16 + grp + (k >> 1)*8;
                    int cl = wn*32 + nf*8 + 2*qid + (k & 1);
                    if (!dg || rl != cl) {
                        float e = exp2f(x * 14.426950408889634f);   // exp(10x)
                        rs[mf*2 + (k >> 1)] += e;
                        ssum += dg ? x : 2.0f * x;
                        if (!dg) cs[nf*2 + (k & 1)] += e;
                    }
                }
            }
        }
        // row partials: reduce over qid lanes, RED into g_rowE[itC*128 + row]
        #pragma unroll
        for (int i = 0; i < 8; i++) {
            rs[i] += __shfl_xor_sync(~0u, rs[i], 1);
            rs[i] += __shfl_xor_sync(~0u, rs[i], 2);
        }
        if (qid == 0) {
            #pragma unroll
            for (int mf = 0; mf < 4; mf++)
                #pragma unroll
                for (int h = 0; h < 2; h++)
                    atomicAdd(&g_rowE[itC*TM + wm*64 + mf*16 + h*8 + grp], rs[mf*2 + h]);
        }
        // col partials (symmetry): reduce over grp lanes, RED into g_rowE[jtC*128 + col]
        if (!dg) {
            #pragma unroll
            for (int i = 0; i < 8; i++) {
                cs[i] += __shfl_xor_sync(~0u, cs[i], 4);
                cs[i] += __shfl_xor_sync(~0u, cs[i], 8);
                cs[i] += __shfl_xor_sync(~0u, cs[i], 16);
            }
            if (grp == 0) {
                #pragma unroll
                for (int nf = 0; nf < 4; nf++)
                    #pragma unroll
                    for (int par = 0; par < 2; par++)
                        atomicAdd(&g_rowE[jtC*TM + wn*32 + nf*8 + 2*qid + par], cs[nf*2 + par]);
            }
        }

        aFresh = nextAFresh;
        itC = itN; jtC = jtN;
        itN = itN2; jtN = jtN2;
        stepPair(itN2, jtN2);
    }

    // ---- block reduce ssum ----
    #pragma unroll
    for (int o = 16; o > 0; o >>= 1) ssum += __shfl_xor_sync(~0u, ssum, o);
    __shared__ float ws[8];
    if (lane == 0) ws[warp] = ssum;
    __syncthreads();
    if (tid == 0) {
        float s = 0.f;
        #pragma unroll
        for (int i = 0; i < 8; i++) s += ws[i];
        g_sPart[b] = s;
    }
}

// ================= kernel 3: finalize =================
__global__ void __launch_bounds__(256) finalize_kernel(float* __restrict__ out) {
    const int tid = threadIdx.x;
    __shared__ float buf[8];
    float lsum = 0.f;
    for (int i = tid; i < TBROWS; i += 256)
        lsum += logf(g_rowE[i]);
    float ssum = (tid < GRID_S) ? g_sPart[tid] : 0.f;
    float psum = g_posPart[tid] + g_posPart[tid + 256];

    float vals[3] = {lsum, ssum, psum};
    float tot[3];
    #pragma unroll
    for (int v = 0; v < 3; v++) {
        float x = vals[v];
        #pragma unroll
        for (int o = 16; o > 0; o >>= 1) x += __shfl_xor_sync(~0u, x, o);
        if ((tid & 31) == 0) buf[tid >> 5] = x;
        __syncthreads();
        float r = 0.f;
        if (tid == 0) {
            #pragma unroll
            for (int i = 0; i < 8; i++) r += buf[i];
        }
        __syncthreads();
        tot[v] = r;
    }
    if (tid == 0) {
        double logSum = tot[0], sSum = tot[1], posSum = tot[2];
        double negMean = (10.0 * sSum - (double)(TBROWS - 1) * logSum)
                       / (4.0 * (double)BROWS * (double)BROWS);
        out[0] = (float)(-(posSum / (double)BROWS) * 10.0 + negMean);
    }
}

// ================= launch =================
extern "C" void kernel_launch(void* const* d_in, const int* in_sizes, int n_in,
                              void* d_out, int out_size) {
    const float* x1 = (const float*)d_in[0];
    const float* x2 = (const float*)d_in[1];
    float* out = (float*)d_out;

    normalize_kernel<<<512, 256>>>(x1, x2);
    cudaFuncSetAttribute(sim_kernel, cudaFuncAttributeMaxDynamicSharedMemorySize, SM_TOTAL);
    sim_kernel<<<GRID_S, 256, SM_TOTAL>>>();
    finalize_kernel<<<1, 256>>>(out);
}

// round 6
// speedup vs baseline: 3.1714x; 1.4561x over previous
#include <cuda_runtime.h>
#include <cuda_bf16.h>
#include <cstdint>

// ContrastiveLoss B=4096, F=256.
// loss = -mean(pos)/T + [10*sum_offdiag(s) - (2B-1)*sum_i LSE_i]/(4B^2)
// R6: s via INT8 mma.sync m16n8k32 (q=round(127c), exact int dot, s=i/16129),
// upper-triangle tiles only (symmetric), sum_offdiag(s) = ||sum_i c_i||^2 - 2B (analytic),
// grid 296 (2 CTAs/SM) for cross-CTA pipe overlap.

#define BROWS  4096
#define FDIM   256
#define TBROWS 8192
#define TM     128
#define NTILES 64
#define NPAIRS 2080
#define GRID_S 296
#define GROWB  256                     // gmem row bytes (256 int8)
#define SSTR   272                     // smem row stride (16B pad: conflict-free ldmatrix)
#define TILE_SM (TM * SSTR)            // 34816
#define TILE_GM (TM * GROWB)           // 32768

// ---------------- scratch ----------------
__device__ __align__(16) int8_t g_Cq[TBROWS * FDIM];     // 2 MB quantized
__device__ float g_rowE[TBROWS];
__device__ float g_colPart[512 * FDIM];                  // per-block feature sums
__device__ float g_posPart[512];

// ================= kernel 1: normalize + quantize + pos sim + colsums =================
__global__ void __launch_bounds__(256) normalize_kernel(
    const float* __restrict__ x1, const float* __restrict__ x2)
{
    int gid = blockIdx.x * 256 + threadIdx.x;
    if (gid < TBROWS) g_rowE[gid] = 0.f;          // fresh accumulators per launch/replay

    int warp = threadIdx.x >> 5, lane = threadIdx.x & 31;
    int r = blockIdx.x * 8 + warp;
    const float4* a4 = reinterpret_cast<const float4*>(x1 + (size_t)r * FDIM);
    const float4* b4 = reinterpret_cast<const float4*>(x2 + (size_t)r * FDIM);
    float4 a0 = a4[lane], a1 = a4[lane + 32];     // features 4l..4l+3, 128+4l..+3
    float4 b0 = b4[lane], b1 = b4[lane + 32];

    float ss1 = a0.x*a0.x+a0.y*a0.y+a0.z*a0.z+a0.w*a0.w + a1.x*a1.x+a1.y*a1.y+a1.z*a1.z+a1.w*a1.w;
    float ss2 = b0.x*b0.x+b0.y*b0.y+b0.z*b0.z+b0.w*b0.w + b1.x*b1.x+b1.y*b1.y+b1.z*b1.z+b1.w*b1.w;
    float dt  = a0.x*b0.x+a0.y*b0.y+a0.z*b0.z+a0.w*b0.w + a1.x*b1.x+a1.y*b1.y+a1.z*b1.z+a1.w*b1.w;
    #pragma unroll
    for (int o = 16; o > 0; o >>= 1) {
        ss1 += __shfl_xor_sync(~0u, ss1, o);
        ss2 += __shfl_xor_sync(~0u, ss2, o);
        dt  += __shfl_xor_sync(~0u, dt,  o);
    }
    float inv1 = 1.0f / fmaxf(sqrtf(ss1), 1e-7f);
    float inv2 = 1.0f / fmaxf(sqrtf(ss2), 1e-7f);

    // quantize: q = round(127*c), pack 8 bytes per row chunk
    float av[8] = {a0.x,a0.y,a0.z,a0.w,a1.x,a1.y,a1.z,a1.w};
    float bv[8] = {b0.x,b0.y,b0.z,b0.w,b1.x,b1.y,b1.z,b1.w};
    int8_t qa[8], qb[8];
    #pragma unroll
    for (int j = 0; j < 8; j++) {
        qa[j] = (int8_t)__float2int_rn(127.f * av[j] * inv1);
        qb[j] = (int8_t)__float2int_rn(127.f * bv[j] * inv2);
    }
    char* o1 = reinterpret_cast<char*>(g_Cq) + (size_t)r * FDIM;
    char* o2 = reinterpret_cast<char*>(g_Cq) + (size_t)(r + BROWS) * FDIM;
    *reinterpret_cast<uint32_t*>(o1 + 4*lane)       = *reinterpret_cast<uint32_t*>(qa);
    *reinterpret_cast<uint32_t*>(o1 + 128 + 4*lane) = *reinterpret_cast<uint32_t*>(qa + 4);
    *reinterpret_cast<uint32_t*>(o2 + 4*lane)       = *reinterpret_cast<uint32_t*>(qb);
    *reinterpret_cast<uint32_t*>(o2 + 128 + 4*lane) = *reinterpret_cast<uint32_t*>(qb + 4);

    // per-block feature sums (fp32 normalized values)
    __shared__ float csm[FDIM];
    __shared__ float ps[8];
    if (threadIdx.x < FDIM) csm[threadIdx.x] = 0.f;
    __syncthreads();
    #pragma unroll
    for (int j = 0; j < 4; j++) {
        atomicAdd(&csm[4*lane + j],       av[j]   * inv1 + bv[j]   * inv2);
        atomicAdd(&csm[128 + 4*lane + j], av[4+j] * inv1 + bv[4+j] * inv2);
    }
    if (lane == 0) ps[warp] = dt * inv1 * inv2;
    __syncthreads();
    if (threadIdx.x < FDIM)
        g_colPart[(size_t)blockIdx.x * FDIM + threadIdx.x] = csm[threadIdx.x];
    if (threadIdx.x == 0) {
        float s = 0.f;
        #pragma unroll
        for (int i = 0; i < 8; i++) s += ps[i];
        g_posPart[blockIdx.x] = s;
    }
}

// ================= helpers =================
__device__ __forceinline__ uint32_t smem_u32(const void* p) {
    uint32_t a;
    asm("{ .reg .u64 t; cvta.to.shared.u64 t, %1; cvt.u32.u64 %0, t; }" : "=r"(a) : "l"(p));
    return a;
}
#define CP16(dst, src) \
    asm volatile("cp.async.cg.shared.global [%0], [%1], 16;" :: "r"(dst), "l"(src) : "memory")
#define CP_COMMIT() asm volatile("cp.async.commit_group;" ::: "memory")
#define CP_WAIT0()  asm volatile("cp.async.wait_group 0;" ::: "memory")
#define CP_WAIT1()  asm volatile("cp.async.wait_group 1;" ::: "memory")

#define LDM4(R, ADDR) \
    asm volatile("ldmatrix.sync.aligned.m8n8.x4.shared.b16 {%0,%1,%2,%3}, [%4];" \
        : "=r"((R)[0]), "=r"((R)[1]), "=r"((R)[2]), "=r"((R)[3]) : "r"(ADDR))

#define MMAI8(ACC, RA, B0, B1) \
    asm volatile("mma.sync.aligned.m16n8k32.row.col.s32.s8.s8.s32 " \
        "{%0,%1,%2,%3},{%4,%5,%6,%7},{%8,%9},{%0,%1,%2,%3};" \
        : "+r"((ACC)[0]), "+r"((ACC)[1]), "+r"((ACC)[2]), "+r"((ACC)[3]) \
        : "r"((RA)[0]), "r"((RA)[1]), "r"((RA)[2]), "r"((RA)[3]), "r"(B0), "r"(B1))

__device__ __forceinline__ void cp_tile(uint32_t dstBase, const char* src, int tid) {
    #pragma unroll
    for (int i = 0; i < 8; i++) {
        int idx = tid + i * 256;
        int row = idx >> 4, c = idx & 15;
        CP16(dstBase + row * SSTR + c * 16, src + row * GROWB + c * 16);
    }
}
__device__ __forceinline__ void stepPair(int& it, int& jt) {
    if (++jt == NTILES) { ++it; jt = it; }
}

#define SM_A  0
#define SM_B0 TILE_SM
#define SM_B1 (2 * TILE_SM)
#define SM_TOTAL (3 * TILE_SM)    // 104448 -> 2 CTAs/SM

// ================= kernel 2: int8 triangle GEMM + symmetric exp epilogue =================
__global__ void __launch_bounds__(256, 2) sim_kernel() {
    extern __shared__ char smem[];
    const uint32_t sb = smem_u32(smem);
    const int tid = threadIdx.x, warp = tid >> 5, lane = tid & 31;
    const int wm = warp >> 2, wn = warp & 3;      // warp tile 64x32
    const int grp = lane >> 2, qid = lane & 3;
    const int b = blockIdx.x;

    const int cnt = 7 + (b < 8);                  // 296*7 + 8 = 2080
    const int p0  = b * 7 + (b < 8 ? b : 8);
    int itC = 0, cum = 0;
    while (cum + (NTILES - itC) <= p0) { cum += NTILES - itC; ++itC; }
    int jtC = itC + (p0 - cum);
    int itN = itC, jtN = jtC;   stepPair(itN, jtN);
    int itN2 = itN, jtN2 = jtN; stepPair(itN2, jtN2);

    const char* gC = reinterpret_cast<const char*>(g_Cq);

    cp_tile(sb + SM_A,  gC + (size_t)itC * TILE_GM, tid);
    cp_tile(sb + SM_B0, gC + (size_t)jtC * TILE_GM, tid);
    CP_COMMIT();
    cp_tile(sb + SM_B1, gC + (size_t)jtN * TILE_GM, tid);
    CP_COMMIT();

    const uint32_t lrow = lane & 15, lhi = (lane >> 4) * 16;
    uint32_t aOff[4], bOff[2];
    #pragma unroll
    for (int mf = 0; mf < 4; mf++) aOff[mf] = sb + SM_A + (wm * 64 + mf * 16 + lrow) * SSTR + lhi;
    #pragma unroll
    for (int h = 0; h < 2; h++)    bOff[h] = (wn * 32 + h * 16 + lrow) * SSTR + lhi;

    bool aFresh = false;
    const float SC = 14.426950408889634f / 16129.0f;   // exp(10*i/127^2) = exp2(i*SC)

    for (int t = 0; t < cnt; t++) {
        if (aFresh) CP_WAIT0(); else CP_WAIT1();
        __syncthreads();
        const uint32_t bB = sb + ((t & 1) ? SM_B1 : SM_B0);

        int acc[4][4][4];
        #pragma unroll
        for (int mf = 0; mf < 4; mf++)
            #pragma unroll
            for (int nf = 0; nf < 4; nf++)
                #pragma unroll
                for (int k = 0; k < 4; k++) acc[mf][nf][k] = 0;

        #pragma unroll
        for (int kk = 0; kk < 8; kk++) {           // K=256, 32 bytes per step
            uint32_t ra[4][4], rb[2][4];
            #pragma unroll
            for (int mf = 0; mf < 4; mf++) LDM4(ra[mf], aOff[mf] + kk * 32);
            #pragma unroll
            for (int h = 0; h < 2; h++)    LDM4(rb[h], bB + bOff[h] + kk * 32);
            #pragma unroll
            for (int mf = 0; mf < 4; mf++) {
                #pragma unroll
                for (int h = 0; h < 2; h++) {
                    MMAI8(acc[mf][2*h+0], ra[mf], rb[h][0], rb[h][2]);
                    MMAI8(acc[mf][2*h+1], ra[mf], rb[h][1], rb[h][3]);
                }
            }
        }
        __syncthreads();

        bool nextAFresh = false;
        if (t + 2 < cnt) cp_tile(bB, gC + (size_t)jtN2 * TILE_GM, tid);
        if (t + 1 < cnt && itN != itC) {
            cp_tile(sb + SM_A, gC + (size_t)itN * TILE_GM, tid);
            nextAFresh = true;
        }
        CP_COMMIT();

        // ---- epilogue: exp + symmetric row/col accumulation ----
        const bool dg = (itC == jtC);
        float rs[8], cs[8];
        #pragma unroll
        for (int i = 0; i < 8; i++) { rs[i] = 0.f; cs[i] = 0.f; }

        #pragma unroll
        for (int mf = 0; mf < 4; mf++) {
            #pragma unroll
            for (int nf = 0; nf < 4; nf++) {
                #pragma unroll
                for (int k = 0; k < 4; k++) {
                    int rl = wm*64 + mf*16 + grp + (k >> 1)*8;
                    int cl = wn*32 + nf*8 + 2*qid + (k & 1);
                    if (!dg || rl != cl) {
                        float e = exp2f((float)acc[mf][nf][k] * SC);
                        rs[mf*2 + (k >> 1)] += e;
                        if (!dg) cs[nf*2 + (k & 1)] += e;
                    }
                }
            }
        }
        #pragma unroll
        for (int i = 0; i < 8; i++) {
            rs[i] += __shfl_xor_sync(~0u, rs[i], 1);
            rs[i] += __shfl_xor_sync(~0u, rs[i], 2);
        }
        if (qid == 0) {
            #pragma unroll
            for (int mf = 0; mf < 4; mf++)
                #pragma unroll
                for (int h = 0; h < 2; h++)
                    atomicAdd(&g_rowE[itC*TM + wm*64 + mf*16 + h*8 + grp], rs[mf*2 + h]);
        }
        if (!dg) {
            #pragma unroll
            for (int i = 0; i < 8; i++) {
                cs[i] += __shfl_xor_sync(~0u, cs[i], 4);
                cs[i] += __shfl_xor_sync(~0u, cs[i], 8);
                cs[i] += __shfl_xor_sync(~0u, cs[i], 16);
            }
            if (grp == 0) {
                #pragma unroll
                for (int nf = 0; nf < 4; nf++)
                    #pragma unroll
                    for (int par = 0; par < 2; par++)
                        atomicAdd(&g_rowE[jtC*TM + wn*32 + nf*8 + 2*qid + par], cs[nf*2 + par]);
            }
        }

        aFresh = nextAFresh;
        itC = itN; jtC = jtN;
        itN = itN2; jtN = jtN2;
        stepPair(itN2, jtN2);
    }
}

// ================= kernel 3: finalize =================
__global__ void __launch_bounds__(256) finalize_kernel(float* __restrict__ out) {
    const int tid = threadIdx.x;
    __shared__ float buf[8];

    float lsum = 0.f;
    for (int i = tid; i < TBROWS; i += 256)
        lsum += logf(g_rowE[i]);

    float v = 0.f;                                 // column sum for feature tid
    for (int bb = 0; bb < 512; bb++)
        v += g_colPart[(size_t)bb * FDIM + tid];
    float s2 = v * v;                              // -> sum_f v^2 = ||sum_i c_i||^2

    float psum = g_posPart[tid] + g_posPart[tid + 256];

    float vals[3] = {lsum, s2, psum};
    float tot[3];
    #pragma unroll
    for (int vv = 0; vv < 3; vv++) {
        float x = vals[vv];
        #pragma unroll
        for (int o = 16; o > 0; o >>= 1) x += __shfl_xor_sync(~0u, x, o);
        if ((tid & 31) == 0) buf[tid >> 5] = x;
        __syncthreads();
        float r = 0.f;
        if (tid == 0) {
            #pragma unroll
            for (int i = 0; i < 8; i++) r += buf[i];
        }
        __syncthreads();
        tot[vv] = r;
    }
    if (tid == 0) {
        double logSum = tot[0];
        double sSum   = (double)tot[1] - (double)TBROWS;   // sum_offdiag s
        double posSum = tot[2];
        double negMean = (10.0 * sSum - (double)(TBROWS - 1) * logSum)
                       / (4.0 * (double)BROWS * (double)BROWS);
        out[0] = (float)(-(posSum / (double)BROWS) * 10.0 + negMean);
    }
}

// ================= launch =================
extern "C" void kernel_launch(void* const* d_in, const int* in_sizes, int n_in,
                              void* d_out, int out_size) {
    const float* x1 = (const float*)d_in[0];
    const float* x2 = (const float*)d_in[1];
    float* out = (float*)d_out;

    normalize_kernel<<<512, 256>>>(x1, x2);
    cudaFuncSetAttribute(sim_kernel, cudaFuncAttributeMaxDynamicSharedMemorySize, SM_TOTAL);
    sim_kernel<<<GRID_S, 256, SM_TOTAL>>>();
    finalize_kernel<<<1, 256>>>(out);
}

// round 7
// speedup vs baseline: 3.7430x; 1.1802x over previous
#include <cuda_runtime.h>
#include <cuda_bf16.h>
#include <cstdint>

// ContrastiveLoss B=4096, F=256.
// loss = -mean(pos)/T + [10*sum_offdiag(s) - (2B-1)*sum_i LSE_i]/(4B^2)
// INT8 mma.sync m16n8k32 (q=round(127c), s=i/16129), upper-triangle tiles only,
// sum_offdiag(s) = ||sum_i c_i||^2 - 2B (analytic). R7: epilogue before barrier
// (intra-CTA MMA/exp overlap), colV direct-RED, finalize self-re-zeroes state.

#define BROWS  4096
#define FDIM   256
#define TBROWS 8192
#define TM     128
#define NTILES 64
#define GRID_S 296
#define GROWB  256
#define SSTR   272
#define TILE_SM (TM * SSTR)            // 34816
#define TILE_GM (TM * GROWB)           // 32768

// ---------------- scratch (zero-init at module load; finalize re-zeroes) ----------------
__device__ __align__(16) int8_t g_Cq[TBROWS * FDIM];
__device__ float g_rowE[TBROWS];
__device__ float g_colV[FDIM];
__device__ float g_posPart[512];

// ================= kernel 1: normalize + quantize + pos sim + colsum RED =================
__global__ void __launch_bounds__(256) normalize_kernel(
    const float* __restrict__ x1, const float* __restrict__ x2)
{
    int warp = threadIdx.x >> 5, lane = threadIdx.x & 31;
    int r = blockIdx.x * 8 + warp;
    const float4* a4 = reinterpret_cast<const float4*>(x1 + (size_t)r * FDIM);
    const float4* b4 = reinterpret_cast<const float4*>(x2 + (size_t)r * FDIM);
    float4 a0 = a4[lane], a1 = a4[lane + 32];     // features 4l..4l+3, 128+4l..+3
    float4 b0 = b4[lane], b1 = b4[lane + 32];

    float ss1 = a0.x*a0.x+a0.y*a0.y+a0.z*a0.z+a0.w*a0.w + a1.x*a1.x+a1.y*a1.y+a1.z*a1.z+a1.w*a1.w;
    float ss2 = b0.x*b0.x+b0.y*b0.y+b0.z*b0.z+b0.w*b0.w + b1.x*b1.x+b1.y*b1.y+b1.z*b1.z+b1.w*b1.w;
    float dt  = a0.x*b0.x+a0.y*b0.y+a0.z*b0.z+a0.w*b0.w + a1.x*b1.x+a1.y*b1.y+a1.z*b1.z+a1.w*b1.w;
    #pragma unroll
    for (int o = 16; o > 0; o >>= 1) {
        ss1 += __shfl_xor_sync(~0u, ss1, o);
        ss2 += __shfl_xor_sync(~0u, ss2, o);
        dt  += __shfl_xor_sync(~0u, dt,  o);
    }
    float inv1 = 1.0f / fmaxf(sqrtf(ss1), 1e-7f);
    float inv2 = 1.0f / fmaxf(sqrtf(ss2), 1e-7f);

    float av[8] = {a0.x,a0.y,a0.z,a0.w,a1.x,a1.y,a1.z,a1.w};
    float bv[8] = {b0.x,b0.y,b0.z,b0.w,b1.x,b1.y,b1.z,b1.w};
    int8_t qa[8], qb[8];
    #pragma unroll
    for (int j = 0; j < 8; j++) {
        qa[j] = (int8_t)__float2int_rn(127.f * av[j] * inv1);
        qb[j] = (int8_t)__float2int_rn(127.f * bv[j] * inv2);
    }
    char* o1 = reinterpret_cast<char*>(g_Cq) + (size_t)r * FDIM;
    char* o2 = reinterpret_cast<char*>(g_Cq) + (size_t)(r + BROWS) * FDIM;
    *reinterpret_cast<uint32_t*>(o1 + 4*lane)       = *reinterpret_cast<uint32_t*>(qa);
    *reinterpret_cast<uint32_t*>(o1 + 128 + 4*lane) = *reinterpret_cast<uint32_t*>(qa + 4);
    *reinterpret_cast<uint32_t*>(o2 + 4*lane)       = *reinterpret_cast<uint32_t*>(qb);
    *reinterpret_cast<uint32_t*>(o2 + 128 + 4*lane) = *reinterpret_cast<uint32_t*>(qb + 4);

    // column sums: per-warp smem slices (no atomics), then one global RED per feature
    __shared__ float wsm[8 * FDIM];
    __shared__ float ps[8];
    float* ws = wsm + warp * FDIM;
    #pragma unroll
    for (int j = 0; j < 4; j++) {
        ws[4*lane + j]       = av[j]   * inv1 + bv[j]   * inv2;
        ws[128 + 4*lane + j] = av[4+j] * inv1 + bv[4+j] * inv2;
    }
    if (lane == 0) ps[warp] = dt * inv1 * inv2;
    __syncthreads();
    {
        int f = threadIdx.x;        // 256 threads == 256 features
        float v = 0.f;
        #pragma unroll
        for (int w = 0; w < 8; w++) v += wsm[w * FDIM + f];
        atomicAdd(&g_colV[f], v);
    }
    if (threadIdx.x == 0) {
        float s = 0.f;
        #pragma unroll
        for (int i = 0; i < 8; i++) s += ps[i];
        g_posPart[blockIdx.x] = s;
    }
}

// ================= helpers =================
__device__ __forceinline__ uint32_t smem_u32(const void* p) {
    uint32_t a;
    asm("{ .reg .u64 t; cvta.to.shared.u64 t, %1; cvt.u32.u64 %0, t; }" : "=r"(a) : "l"(p));
    return a;
}
#define CP16(dst, src) \
    asm volatile("cp.async.cg.shared.global [%0], [%1], 16;" :: "r"(dst), "l"(src) : "memory")
#define CP_COMMIT() asm volatile("cp.async.commit_group;" ::: "memory")
#define CP_WAIT0()  asm volatile("cp.async.wait_group 0;" ::: "memory")
#define CP_WAIT1()  asm volatile("cp.async.wait_group 1;" ::: "memory")

#define LDM4(R, ADDR) \
    asm volatile("ldmatrix.sync.aligned.m8n8.x4.shared.b16 {%0,%1,%2,%3}, [%4];" \
        : "=r"((R)[0]), "=r"((R)[1]), "=r"((R)[2]), "=r"((R)[3]) : "r"(ADDR))

#define MMAI8(ACC, RA, B0, B1) \
    asm volatile("mma.sync.aligned.m16n8k32.row.col.s32.s8.s8.s32 " \
        "{%0,%1,%2,%3},{%4,%5,%6,%7},{%8,%9},{%0,%1,%2,%3};" \
        : "+r"((ACC)[0]), "+r"((ACC)[1]), "+r"((ACC)[2]), "+r"((ACC)[3]) \
        : "r"((RA)[0]), "r"((RA)[1]), "r"((RA)[2]), "r"((RA)[3]), "r"(B0), "r"(B1))

__device__ __forceinline__ void cp_tile(uint32_t dstBase, const char* src, int tid) {
    #pragma unroll
    for (int i = 0; i < 8; i++) {
        int idx = tid + i * 256;
        int row = idx >> 4, c = idx & 15;
        CP16(dstBase + row * SSTR + c * 16, src + row * GROWB + c * 16);
    }
}
__device__ __forceinline__ void stepPair(int& it, int& jt) {
    if (++jt == NTILES) { ++it; jt = it; }
}

#define SM_A  0
#define SM_B0 TILE_SM
#define SM_B1 (2 * TILE_SM)
#define SM_TOTAL (3 * TILE_SM)    // 104448 -> 2 CTAs/SM

// ================= kernel 2: int8 triangle GEMM + overlapped exp epilogue =================
__global__ void __launch_bounds__(256, 2) sim_kernel() {
    extern __shared__ char smem[];
    const uint32_t sb = smem_u32(smem);
    const int tid = threadIdx.x, warp = tid >> 5, lane = tid & 31;
    const int wm = warp >> 2, wn = warp & 3;
    const int grp = lane >> 2, qid = lane & 3;
    const int b = blockIdx.x;

    const int cnt = 7 + (b < 8);                  // 296*7 + 8 = 2080
    const int p0  = b * 7 + (b < 8 ? b : 8);
    int itC = 0, cum = 0;
    while (cum + (NTILES - itC) <= p0) { cum += NTILES - itC; ++itC; }
    int jtC = itC + (p0 - cum);
    int itN = itC, jtN = jtC;   stepPair(itN, jtN);
    int itN2 = itN, jtN2 = jtN; stepPair(itN2, jtN2);

    const char* gC = reinterpret_cast<const char*>(g_Cq);

    cp_tile(sb + SM_A,  gC + (size_t)itC * TILE_GM, tid);
    cp_tile(sb + SM_B0, gC + (size_t)jtC * TILE_GM, tid);
    CP_COMMIT();
    cp_tile(sb + SM_B1, gC + (size_t)jtN * TILE_GM, tid);
    CP_COMMIT();

    const uint32_t lrow = lane & 15, lhi = (lane >> 4) * 16;
    uint32_t aOff[4], bOff[2];
    #pragma unroll
    for (int mf = 0; mf < 4; mf++) aOff[mf] = sb + SM_A + (wm * 64 + mf * 16 + lrow) * SSTR + lhi;
    #pragma unroll
    for (int h = 0; h < 2; h++)    bOff[h] = (wn * 32 + h * 16 + lrow) * SSTR + lhi;

    bool aFresh = false;
    const float SC = 14.426950408889634f / 16129.0f;   // exp(10*i/127^2) = exp2(i*SC)

    for (int t = 0; t < cnt; t++) {
        if (aFresh) CP_WAIT0(); else CP_WAIT1();
        __syncthreads();                           // tiles for t resident
        const uint32_t bB = sb + ((t & 1) ? SM_B1 : SM_B0);

        int acc[4][4][4];
        #pragma unroll
        for (int mf = 0; mf < 4; mf++)
            #pragma unroll
            for (int nf = 0; nf < 4; nf++)
                #pragma unroll
                for (int k = 0; k < 4; k++) acc[mf][nf][k] = 0;

        #pragma unroll
        for (int kk = 0; kk < 8; kk++) {
            uint32_t ra[4][4], rb[2][4];
            #pragma unroll
            for (int mf = 0; mf < 4; mf++) LDM4(ra[mf], aOff[mf] + kk * 32);
            #pragma unroll
            for (int h = 0; h < 2; h++)    LDM4(rb[h], bB + bOff[h] + kk * 32);
            #pragma unroll
            for (int mf = 0; mf < 4; mf++) {
                #pragma unroll
                for (int h = 0; h < 2; h++) {
                    MMAI8(acc[mf][2*h+0], ra[mf], rb[h][0], rb[h][2]);
                    MMAI8(acc[mf][2*h+1], ra[mf], rb[h][1], rb[h][3]);
                }
            }
        }

        // ---- epilogue BEFORE barrier: overlaps other warps' MMA ----
        const bool dg = (itC == jtC);
        float rs[8];
        #pragma unroll
        for (int i = 0; i < 8; i++) rs[i] = 0.f;

        if (!dg) {
            float cs[8];
            #pragma unroll
            for (int i = 0; i < 8; i++) cs[i] = 0.f;
            #pragma unroll
            for (int mf = 0; mf < 4; mf++)
                #pragma unroll
                for (int nf = 0; nf < 4; nf++)
                    #pragma unroll
                    for (int k = 0; k < 4; k++) {
                        float e = exp2f((float)acc[mf][nf][k] * SC);
                        rs[mf*2 + (k >> 1)] += e;
                        cs[nf*2 + (k & 1)] += e;
                    }
            #pragma unroll
            for (int i = 0; i < 8; i++) {
                rs[i] += __shfl_xor_sync(~0u, rs[i], 1);
                rs[i] += __shfl_xor_sync(~0u, rs[i], 2);
                cs[i] += __shfl_xor_sync(~0u, cs[i], 4);
                cs[i] += __shfl_xor_sync(~0u, cs[i], 8);
                cs[i] += __shfl_xor_sync(~0u, cs[i], 16);
            }
            if (qid == 0) {
                #pragma unroll
                for (int mf = 0; mf < 4; mf++)
                    #pragma unroll
                    for (int h = 0; h < 2; h++)
                        atomicAdd(&g_rowE[itC*TM + wm*64 + mf*16 + h*8 + grp], rs[mf*2 + h]);
            }
            if (grp == 0) {
                #pragma unroll
                for (int nf = 0; nf < 4; nf++)
                    #pragma unroll
                    for (int par = 0; par < 2; par++)
                        atomicAdd(&g_rowE[jtC*TM + wn*32 + nf*8 + 2*qid + par], cs[nf*2 + par]);
            }
        } else {
            #pragma unroll
            for (int mf = 0; mf < 4; mf++)
                #pragma unroll
                for (int nf = 0; nf < 4; nf++)
                    #pragma unroll
                    for (int k = 0; k < 4; k++) {
                        int rl = wm*64 + mf*16 + grp + (k >> 1)*8;
                        int cl = wn*32 + nf*8 + 2*qid + (k & 1);
                        if (rl != cl) {
                            float e = exp2f((float)acc[mf][nf][k] * SC);
                            rs[mf*2 + (k >> 1)] += e;
                        }
                    }
            #pragma unroll
            for (int i = 0; i < 8; i++) {
                rs[i] += __shfl_xor_sync(~0u, rs[i], 1);
                rs[i] += __shfl_xor_sync(~0u, rs[i], 2);
            }
            if (qid == 0) {
                #pragma unroll
                for (int mf = 0; mf < 4; mf++)
                    #pragma unroll
                    for (int h = 0; h < 2; h++)
                        atomicAdd(&g_rowE[itC*TM + wm*64 + mf*16 + h*8 + grp], rs[mf*2 + h]);
            }
        }

        __syncthreads();                           // all warps done reading smem tiles
        bool nextAFresh = false;
        if (t + 2 < cnt) cp_tile(bB, gC + (size_t)jtN2 * TILE_GM, tid);
        if (t + 1 < cnt && itN != itC) {
            cp_tile(sb + SM_A, gC + (size_t)itN * TILE_GM, tid);
            nextAFresh = true;
        }
        CP_COMMIT();

        aFresh = nextAFresh;
        itC = itN; jtC = jtN;
        itN = itN2; jtN = jtN2;
        stepPair(itN2, jtN2);
    }
}

// ================= kernel 3: finalize (re-zeroes accumulators for next replay) =================
__global__ void __launch_bounds__(256) finalize_kernel(float* __restrict__ out) {
    const int tid = threadIdx.x;
    __shared__ float buf[8];

    float lsum = 0.f;
    for (int i = tid; i < TBROWS; i += 256) {
        lsum += logf(g_rowE[i]);
        g_rowE[i] = 0.f;                           // reset for next launch/replay
    }
    float v = g_colV[tid];
    g_colV[tid] = 0.f;                             // reset
    float s2 = v * v;
    float psum = g_posPart[tid] + g_posPart[tid + 256];

    float vals[3] = {lsum, s2, psum};
    float tot[3];
    #pragma unroll
    for (int vv = 0; vv < 3; vv++) {
        float x = vals[vv];
        #pragma unroll
        for (int o = 16; o > 0; o >>= 1) x += __shfl_xor_sync(~0u, x, o);
        if ((tid & 31) == 0) buf[tid >> 5] = x;
        __syncthreads();
        float r = 0.f;
        if (tid == 0) {
            #pragma unroll
            for (int i = 0; i < 8; i++) r += buf[i];
        }
        __syncthreads();
        tot[vv] = r;
    }
    if (tid == 0) {
        double logSum = tot[0];
        double sSum   = (double)tot[1] - (double)TBROWS;   // sum_offdiag s
        double posSum = tot[2];
        double negMean = (10.0 * sSum - (double)(TBROWS - 1) * logSum)
                       / (4.0 * (double)BROWS * (double)BROWS);
        out[0] = (float)(-(posSum / (double)BROWS) * 10.0 + negMean);
    }
}

// ================= launch =================
extern "C" void kernel_launch(void* const* d_in, const int* in_sizes, int n_in,
                              void* d_out, int out_size) {
    const float* x1 = (const float*)d_in[0];
    const float* x2 = (const float*)d_in[1];
    float* out = (float*)d_out;

    normalize_kernel<<<512, 256>>>(x1, x2);
    cudaFuncSetAttribute(sim_kernel, cudaFuncAttributeMaxDynamicSharedMemorySize, SM_TOTAL);
    sim_kernel<<<GRID_S, 256, SM_TOTAL>>>();
    finalize_kernel<<<1, 256>>>(out);
}